// round 8
// baseline (speedup 1.0000x reference)
#include <cuda_runtime.h>
#include <math.h>
#include <cstdint>

#define NTOT 16384
#define AS_F 4608          // 128*36 floats (A plane)
#define BS_F 2304          // 64*36 floats (B plane)
#define PL_F (AS_F + BS_F) // 6912 floats per 32-k plane
#define STAGE_F (2 * PL_F) // 64-k stage = two planes
#define ROW36 (32 * 36)

// ---------------- scratch (device globals; no allocation allowed) ----------
__device__ __align__(16) float g_x[131072 * 64];    // encoder out (fp32)
__device__ __align__(16) float g_wtf[503808];       // tf32-rounded weights pool
__device__ __align__(16) float g_aq[NTOT * 8];
__device__ __align__(16) float g_h1[NTOT * 256];
__device__ __align__(16) float g_hf[NTOT * 256];
__device__ __align__(16) float g_w1[NTOT * 512];
__device__ __align__(16) float g_wf[NTOT * 64];
__device__ __align__(16) float g_b1[NTOT * 64];
__device__ __align__(16) float g_v1[NTOT * 64];

// offsets (floats) in g_wtf
#define OFF_WOBS 0
#define OFF_WQKV 16384
#define OFF_WH1A 28672
#define OFF_WHFA 159744
#define OFF_WH1B 290816
#define OFF_WHFB 421888
#define OFF_WB1  438272
#define OFF_WV1  471040
#define WTF_TOTAL 503808

// ---------------- helpers ---------------------------------------------------
__device__ __forceinline__ uint32_t f2tf(float x) {   // RNA round to tf32
    uint32_t r;
    asm("cvt.rna.tf32.f32 %0, %1;" : "=r"(r) : "f"(x));
    return r;
}
__device__ __forceinline__ uint32_t smem_u32(const void* p) {
    uint32_t a;
    asm("{ .reg .u64 t; cvta.to.shared.u64 t, %1; cvt.u32.u64 %0, t; }" : "=r"(a) : "l"(p));
    return a;
}
__device__ __forceinline__ void cp16(uint32_t s, const void* g) {
    asm volatile("cp.async.cg.shared.global [%0], [%1], 16;" :: "r"(s), "l"(g));
}
#define CP_COMMIT asm volatile("cp.async.commit_group;" ::: "memory")
#define CP_WAIT(N) asm volatile("cp.async.wait_group %0;" :: "n"(N) : "memory")

__device__ __forceinline__ void mma_tf32(float* c, const uint32_t* a, const uint32_t* b) {
    asm volatile(
        "mma.sync.aligned.m16n8k8.row.col.f32.tf32.tf32.f32 "
        "{%0,%1,%2,%3}, {%4,%5,%6,%7}, {%8,%9}, {%0,%1,%2,%3};\n"
        : "+f"(c[0]), "+f"(c[1]), "+f"(c[2]), "+f"(c[3])
        : "r"(a[0]), "r"(a[1]), "r"(a[2]), "r"(a[3]), "r"(b[0]), "r"(b[1]));
}

// ---- compute one 128x64x32 plane from [r][36] tiles ------------------------
// k-slot permutation: logical k = 8t + 2*kk8 + half (applied to A & B)
template <int CVTA>
__device__ __forceinline__ void compute_chunk(
    const float* __restrict__ Ab, const float* __restrict__ Bb,
    float acc[2][4][4], int wm, int wn, int g, int t)
{
    float a8[4][8], b8[4][8];
#pragma unroll
    for (int i = 0; i < 4; i++) {
        const float* pr = Ab + (wm * 32 + i * 8 + g) * 36 + t * 8;
        *(float4*)&a8[i][0] = *(const float4*)pr;
        *(float4*)&a8[i][4] = *(const float4*)(pr + 4);
    }
#pragma unroll
    for (int i = 0; i < 4; i++) {
        const float* pr = Bb + (wn * 32 + i * 8 + g) * 36 + t * 8;
        *(float4*)&b8[i][0] = *(const float4*)pr;
        *(float4*)&b8[i][4] = *(const float4*)(pr + 4);
    }
#pragma unroll
    for (int k8 = 0; k8 < 4; k8++) {
        uint32_t af[2][4], bf[4][2];
#pragma unroll
        for (int mi = 0; mi < 2; mi++) {
            if (CVTA) {
                af[mi][0] = f2tf(a8[2 * mi][2 * k8]);
                af[mi][1] = f2tf(a8[2 * mi + 1][2 * k8]);
                af[mi][2] = f2tf(a8[2 * mi][2 * k8 + 1]);
                af[mi][3] = f2tf(a8[2 * mi + 1][2 * k8 + 1]);
            } else {
                af[mi][0] = __float_as_uint(a8[2 * mi][2 * k8]);
                af[mi][1] = __float_as_uint(a8[2 * mi + 1][2 * k8]);
                af[mi][2] = __float_as_uint(a8[2 * mi][2 * k8 + 1]);
                af[mi][3] = __float_as_uint(a8[2 * mi + 1][2 * k8 + 1]);
            }
        }
#pragma unroll
        for (int ni = 0; ni < 4; ni++) {
            bf[ni][0] = __float_as_uint(b8[ni][2 * k8]);
            bf[ni][1] = __float_as_uint(b8[ni][2 * k8 + 1]);
        }
#pragma unroll
        for (int mi = 0; mi < 2; mi++)
#pragma unroll
            for (int ni = 0; ni < 4; ni++)
                mma_tf32(acc[mi][ni], af[mi], bf[ni]);
    }
}

// ---- stage one 64-k chunk (two 32-k planes) via cp.async -------------------
// Ab/Bb: per-thread gmem ptrs (row tid>>3, col (tid&7)*4, at chunk base).
// sa/sb: per-thread smem byte addrs inside the target stage buffer.
__device__ __forceinline__ void issue_stage64(
    const float* __restrict__ Ab, const float* __restrict__ Bb, int K,
    uint32_t sa, uint32_t sb)
{
#pragma unroll
    for (int p = 0; p < 2; p++) {
#pragma unroll
        for (int i = 0; i < 4; i++)
            cp16(sa + (uint32_t)(p * PL_F + i * ROW36) * 4, Ab + p * 32 + (size_t)i * 32 * K);
#pragma unroll
        for (int i = 0; i < 2; i++)
            cp16(sb + (uint32_t)(p * PL_F + i * ROW36) * 4, Bb + p * 32 + (size_t)i * 32 * K);
    }
}

// 2-stage, BK=64, ONE wait + ONE barrier per 64-k.
// Safety: the in-loop issue targets buf (c+1)&1, last read at compute(c-1);
// the barrier (placed after the wait, before the issue) orders all warps
// past compute(c-1). Requires nk64 >= 1.
template <int CVTA>
__device__ __forceinline__ void gemm_main64(
    const float* __restrict__ A, const float* __restrict__ B, int K,
    int row0, int col0, float* Sm, float acc[2][4][4],
    int tid, int wm, int wn, int g, int t)
{
    const uint32_t su = smem_u32(Sm);
    const int ra = tid >> 3, q4 = (tid & 7) * 4;
    const float* Abase = A + (size_t)(row0 + ra) * K + q4;
    const float* Bbase = B + (size_t)(col0 + ra) * K + q4;
    const uint32_t sa = su + (uint32_t)(ra * 36 + q4) * 4;
    const uint32_t sb = sa + (uint32_t)AS_F * 4;
    const int nk = K >> 6;

    issue_stage64(Abase, Bbase, K, sa, sb); CP_COMMIT;
    for (int c = 0; c < nk; c++) {
        CP_WAIT(0);
        __syncthreads();
        if (c + 1 < nk) {
            const uint32_t so = (uint32_t)(((c + 1) & 1) * STAGE_F) * 4;
            issue_stage64(Abase + (c + 1) * 64, Bbase + (c + 1) * 64, K, sa + so, sb + so);
            CP_COMMIT;
        }
        const float* st = Sm + (c & 1) * STAGE_F;
        compute_chunk<CVTA>(st,        st + AS_F,        acc, wm, wn, g, t);
        compute_chunk<CVTA>(st + PL_F, st + PL_F + AS_F, acc, wm, wn, g, t);
    }
}

// ---------------- weight pre-conversion kernel ------------------------------
struct WSeg { const float* src; int off; int cnt; };
struct WSegs { WSeg v[8]; };
#define CVT_W_BLOCKS 492            // WTF_TOTAL / 1024

__global__ void __launch_bounds__(256) cvt_w_kernel(WSegs segs, float* __restrict__ wdst)
{
    int i4 = (blockIdx.x * 256 + threadIdx.x) * 4;
#pragma unroll
    for (int k = 0; k < 8; k++) {
        int off = segs.v[k].off, cnt = segs.v[k].cnt;
        if (i4 >= off && i4 < off + cnt) {
            float4 v = *(const float4*)(segs.v[k].src + (i4 - off));
            uint4 u = { f2tf(v.x), f2tf(v.y), f2tf(v.z), f2tf(v.w) };
            *(uint4*)(wdst + i4) = u;
        }
    }
}

// ---------------- packed GEMM: op table, 1D grid of 128-row tiles -----------
// epi: 0=id, 1=relu, 2=abs, 4=encoder (gather+bias fusion)
struct GOp {
    const float* A; const float* B; const float* bias; float* C;
    int K; int Nout; int col0; int epi; int tileBase; int pad;
};
struct GOps { GOp v[11]; };
#define G_SMEM_BYTES ((2 * STAGE_F + 192) * 4)

__global__ void __launch_bounds__(256, 2) packed_gemm(
    GOps ops,
    const int* __restrict__ actions, const float* __restrict__ qvals,
    const float* __restrict__ W_act, const float* __restrict__ W_q,
    const float* __restrict__ b_act, const float* __restrict__ b_q)
{
    extern __shared__ float dsm[];
    float* bias_sh = dsm + 2 * STAGE_F;
    float* cvec_sh = bias_sh + 64;
    float* wq_sh   = cvec_sh + 64;

    const int bid = blockIdx.x;
    int j = 0;
#pragma unroll
    for (int k = 1; k < 11; k++) if (bid >= ops.v[k].tileBase) j = k;
    const GOp op = ops.v[j];

    const int tid = threadIdx.x;
    const int wid = tid >> 5, lane = tid & 31;
    const int wm = wid >> 1, wn = wid & 1;
    const int g = lane >> 2, t = lane & 3;
    const int row0 = (bid - op.tileBase) * 128;
    const int col0 = op.col0;
    const int epi = op.epi;

    if (tid < 64) {
        bias_sh[tid] = op.bias[col0 + tid];
        if (epi == 4) {
            cvec_sh[tid] = b_act[tid] + b_q[tid];
            wq_sh[tid] = W_q[tid];
        }
    }

    float acc[2][4][4];
#pragma unroll
    for (int mi = 0; mi < 2; mi++)
#pragma unroll
        for (int ni = 0; ni < 4; ni++)
#pragma unroll
            for (int jj = 0; jj < 4; jj++) acc[mi][ni][jj] = 0.f;

    gemm_main64<1>(op.A, op.B, op.K, row0, col0, dsm, acc, tid, wm, wn, g, t);

    const int Nout = op.Nout;
#pragma unroll
    for (int mi = 0; mi < 2; mi++)
#pragma unroll
        for (int half = 0; half < 2; half++) {
            const int row = row0 + wm * 32 + mi * 16 + half * 8 + g;
            int act = 0; float qv = 0.f;
            if (epi == 4) { act = actions[row]; qv = qvals[row]; }
            float* dst = op.C + (size_t)row * Nout + col0;
#pragma unroll
            for (int ni = 0; ni < 4; ni++) {
                const int lc = wn * 32 + ni * 8 + t * 2;
                float v0 = acc[mi][ni][half * 2 + 0] + bias_sh[lc];
                float v1 = acc[mi][ni][half * 2 + 1] + bias_sh[lc + 1];
                if (epi == 4) {
                    v0 += cvec_sh[lc] + __ldg(&W_act[lc * 32 + act]) + qv * wq_sh[lc];
                    v1 += cvec_sh[lc + 1] + __ldg(&W_act[(lc + 1) * 32 + act]) + qv * wq_sh[lc + 1];
                } else if (epi == 1) {
                    v0 = fmaxf(v0, 0.f); v1 = fmaxf(v1, 0.f);
                } else if (epi == 2) {
                    v0 = fabsf(v0); v1 = fabsf(v1);
                }
                float2 o = { v0, v1 };
                *(float2*)(dst + lc) = o;
            }
        }
}

// ---------------- fused qkv GEMM + attention (+ inline wcomb) ---------------
#define QA_XS_F (2 * 128 * 36)
#define QA_WS_F (2 * 192 * 36)
#define QA_QS_F (128 * 196)
#define QA_SMEM_BYTES ((QA_XS_F + QA_WS_F + QA_QS_F + 192 + 65) * 4)

__global__ void __launch_bounds__(256) qkv_attn_kernel(
    const float* __restrict__ Wqkv_tf, const float* __restrict__ bqkv,
    const float* __restrict__ Wa2q, const float* __restrict__ ba2q,
    const float* __restrict__ Wo, const float* __restrict__ bo)
{
    extern __shared__ float sm[];
    float* xs = sm;                        // [2][128][36]
    float* ws = xs + QA_XS_F;              // [2][192][36]
    float* qs = ws + QA_WS_F;              // [128][196]
    float* bq = qs + QA_QS_F;              // 192
    float* wc = bq + 192;                  // 65

    const int tid = threadIdx.x;
    const int wid = tid >> 5, lane = tid & 31;
    const int wm = wid >> 1, wn = wid & 1;
    const int g = lane >> 2, t = lane & 3;
    const int row0 = blockIdx.x * 128;

    const uint32_t xs_u = smem_u32(xs);
    const uint32_t ws_u = smem_u32(ws);
#pragma unroll
    for (int i = 0; i < 8; i++) {          // x tile: 2048 float4
        int e = tid + i * 256;
        int r = e >> 4, q = e & 15;
        cp16(xs_u + (uint32_t)((q >> 3) * (128 * 36) + r * 36 + (q & 7) * 4) * 4,
             g_x + (size_t)(row0 + r) * 64 + q * 4);
    }
#pragma unroll
    for (int i = 0; i < 12; i++) {         // Wqkv: 3072 float4
        int e = tid + i * 256;
        int n = e >> 4, q = e & 15;
        cp16(ws_u + (uint32_t)((q >> 3) * (192 * 36) + n * 36 + (q & 7) * 4) * 4,
             Wqkv_tf + (size_t)n * 64 + q * 4);
    }
    if (tid < 192) bq[tid] = bqkv[tid];
    // inline wcomb = Wa2q @ Wo (hidden under cp.async wait)
    if (tid < 64) {
        float s = 0.f;
#pragma unroll 8
        for (int c = 0; c < 64; c++) s += Wa2q[c] * Wo[c * 64 + tid];
        wc[tid] = s;
    }
    if (wid == 6) {                        // bcomb = Wa2q.bo + ba2q
        float v = Wa2q[lane] * bo[lane] + Wa2q[lane + 32] * bo[lane + 32];
#pragma unroll
        for (int off = 16; off > 0; off >>= 1) v += __shfl_xor_sync(0xffffffffu, v, off);
        if (lane == 0) wc[64] = v + ba2q[0];
    }
    CP_COMMIT; CP_WAIT(0);
    __syncthreads();

    // ---- phase B: qkv = x @ Wqkv^T (3 col blocks of 64) ----
#pragma unroll 1
    for (int cb = 0; cb < 3; cb++) {
        float acc[2][4][4];
#pragma unroll
        for (int mi = 0; mi < 2; mi++)
#pragma unroll
            for (int ni = 0; ni < 4; ni++)
#pragma unroll
                for (int jj = 0; jj < 4; jj++) acc[mi][ni][jj] = 0.f;

#pragma unroll
        for (int c = 0; c < 2; c++)
            compute_chunk<1>(xs + c * (128 * 36),
                             ws + c * (192 * 36) + (cb * 64) * 36,
                             acc, wm, wn, g, t);

#pragma unroll
        for (int mi = 0; mi < 2; mi++)
#pragma unroll
            for (int half = 0; half < 2; half++) {
                const int row = wm * 32 + mi * 16 + half * 8 + g;
#pragma unroll
                for (int ni = 0; ni < 4; ni++) {
                    const int lc = wn * 32 + ni * 8 + t * 2;
                    qs[row * 196 + cb * 64 + lc]     = acc[mi][ni][half * 2 + 0] + bq[cb * 64 + lc];
                    qs[row * 196 + cb * 64 + lc + 1] = acc[mi][ni][half * 2 + 1] + bq[cb * 64 + lc + 1];
                }
            }
    }
    __syncthreads();

    // ---- phase C: attention per sample (2 samples per warp) ----
    const int h = lane >> 3, a = lane & 7;
#pragma unroll
    for (int s2 = 0; s2 < 2; s2++) {
        const int s = wid * 2 + s2;
        const float* base = qs + s * 8 * 196;

        float q[16];
#pragma unroll
        for (int d = 0; d < 16; d++) q[d] = base[a * 196 + h * 16 + d];
        float sc[8], m = -1e30f;
#pragma unroll
        for (int b = 0; b < 8; b++) {
            float acc = 0.f;
#pragma unroll
            for (int d = 0; d < 16; d++) acc += q[d] * base[b * 196 + 64 + h * 16 + d];
            sc[b] = acc * 0.25f;          // 1/sqrt(16)
            m = fmaxf(m, sc[b]);
        }
        float sum = 0.f;
#pragma unroll
        for (int b = 0; b < 8; b++) { sc[b] = __expf(sc[b] - m); sum += sc[b]; }
        float inv = 1.f / sum;
        float o[16];
#pragma unroll
        for (int d = 0; d < 16; d++) o[d] = 0.f;
#pragma unroll
        for (int b = 0; b < 8; b++) {
            float p = sc[b] * inv;
#pragma unroll
            for (int d = 0; d < 16; d++) o[d] += p * base[b * 196 + 128 + h * 16 + d];
        }
        float part = 0.f;
#pragma unroll
        for (int d = 0; d < 16; d++) part += o[d] * wc[h * 16 + d];
        part += __shfl_xor_sync(0xffffffffu, part, 8);
        part += __shfl_xor_sync(0xffffffffu, part, 16);
        if (h == 0) {
            const int n = blockIdx.x * 16 + s;
            g_aq[n * 8 + a] = part + wc[64];
        }
    }
}

// ---------------- final mixing: elu(aq @ w1 + b1) . w_f + v ----------------
__global__ void __launch_bounds__(256) final_kernel(
    const float* __restrict__ Wv2, const float* __restrict__ bv2,
    float* __restrict__ out)
{
    const int warp = threadIdx.x >> 5, lane = threadIdx.x & 31;
    const int n = blockIdx.x * 8 + warp;
    if (n >= NTOT) return;

    float aqv[8];
#pragma unroll
    for (int a = 0; a < 8; a++) aqv[a] = g_aq[n * 8 + a];

    float tot = 0.f;
#pragma unroll
    for (int jj = 0; jj < 2; jj++) {
        int e = jj * 32 + lane;
        float hsum = g_b1[n * 64 + e];
#pragma unroll
        for (int a = 0; a < 8; a++) hsum += aqv[a] * g_w1[(size_t)n * 512 + a * 64 + e];
        float hid = hsum > 0.f ? hsum : expm1f(hsum);
        tot += hid * g_wf[n * 64 + e] + g_v1[n * 64 + e] * Wv2[e];
    }
#pragma unroll
    for (int off = 16; off > 0; off >>= 1) tot += __shfl_xor_sync(0xffffffffu, tot, off);
    if (lane == 0) out[n] = tot + bv2[0];
}

// ---------------- launch ----------------------------------------------------
extern "C" void kernel_launch(void* const* d_in, const int* in_sizes, int n_in,
                              void* d_out, int out_size)
{
    const float* agent_qs = (const float*)d_in[0];
    const float* states   = (const float*)d_in[1];
    const float* obs      = (const float*)d_in[2];
    const int*   actions  = (const int*)d_in[3];
    const float* W_obs = (const float*)d_in[4];  const float* b_obs = (const float*)d_in[5];
    const float* W_act = (const float*)d_in[6];  const float* b_act = (const float*)d_in[7];
    const float* W_q   = (const float*)d_in[8];  const float* b_q   = (const float*)d_in[9];
    const float* Wqkv  = (const float*)d_in[10]; const float* bqkv  = (const float*)d_in[11];
    const float* Wo    = (const float*)d_in[12]; const float* bo    = (const float*)d_in[13];
    const float* Wa2q  = (const float*)d_in[14]; const float* ba2q  = (const float*)d_in[15];
    const float* Wh1a  = (const float*)d_in[16]; const float* bh1a  = (const float*)d_in[17];
    const float* Wh1b  = (const float*)d_in[18]; const float* bh1b  = (const float*)d_in[19];
    const float* Whfa  = (const float*)d_in[20]; const float* bhfa  = (const float*)d_in[21];
    const float* Whfb  = (const float*)d_in[22]; const float* bhfb  = (const float*)d_in[23];
    const float* Wb1   = (const float*)d_in[24]; const float* bb1   = (const float*)d_in[25];
    const float* Wv1   = (const float*)d_in[26]; const float* bv1   = (const float*)d_in[27];
    const float* Wv2   = (const float*)d_in[28]; const float* bv2   = (const float*)d_in[29];
    float* out = (float*)d_out;

    void *p_x, *p_wtf, *p_h1, *p_hf, *p_w1, *p_wf, *p_b1, *p_v1;
    cudaGetSymbolAddress(&p_x,   g_x);
    cudaGetSymbolAddress(&p_wtf, g_wtf);
    cudaGetSymbolAddress(&p_h1,  g_h1);
    cudaGetSymbolAddress(&p_hf,  g_hf);
    cudaGetSymbolAddress(&p_w1,  g_w1);
    cudaGetSymbolAddress(&p_wf,  g_wf);
    cudaGetSymbolAddress(&p_b1,  g_b1);
    cudaGetSymbolAddress(&p_v1,  g_v1);
    float* wtf = (float*)p_wtf;

    cudaFuncSetAttribute(packed_gemm,     cudaFuncAttributeMaxDynamicSharedMemorySize, G_SMEM_BYTES);
    cudaFuncSetAttribute(qkv_attn_kernel, cudaFuncAttributeMaxDynamicSharedMemorySize, QA_SMEM_BYTES);

    // 0) pre-convert weights (B-sides) to tf32-rounded fp32
    WSegs segs;
    segs.v[0] = { W_obs, OFF_WOBS, 16384 };
    segs.v[1] = { Wqkv,  OFF_WQKV, 12288 };
    segs.v[2] = { Wh1a,  OFF_WH1A, 131072 };
    segs.v[3] = { Whfa,  OFF_WHFA, 131072 };
    segs.v[4] = { Wh1b,  OFF_WH1B, 131072 };
    segs.v[5] = { Whfb,  OFF_WHFB, 16384 };
    segs.v[6] = { Wb1,   OFF_WB1,  32768 };
    segs.v[7] = { Wv1,   OFF_WV1,  32768 };
    cvt_w_kernel<<<CVT_W_BLOCKS, 256>>>(segs, wtf);

    // 1) mega launch 1: encoder (1024 tiles) + state hypernets (1280 tiles)
    GOps m1 = {};
    m1.v[0] = { obs,    wtf + OFF_WOBS, b_obs, (float*)p_x,  256, 64, 0, 4, 0, 0 };
    for (int i = 0; i < 4; i++)
        m1.v[1 + i] = { states, wtf + OFF_WH1A, bh1a, (float*)p_h1, 512, 256, i * 64, 1, 1024 + i * 128, 0 };
    for (int i = 0; i < 4; i++)
        m1.v[5 + i] = { states, wtf + OFF_WHFA, bhfa, (float*)p_hf, 512, 256, i * 64, 1, 1536 + i * 128, 0 };
    m1.v[9]  = { states, wtf + OFF_WB1, bb1, (float*)p_b1, 512, 64, 0, 0, 2048, 0 };
    m1.v[10] = { states, wtf + OFF_WV1, bv1, (float*)p_v1, 512, 64, 0, 1, 2176, 0 };
    packed_gemm<<<2304, 256, G_SMEM_BYTES>>>(m1, actions, agent_qs, W_act, W_q, b_act, b_q);

    // 2) fused qkv + attention (wcomb inline) -> attended_qs
    qkv_attn_kernel<<<1024, 256, QA_SMEM_BYTES>>>(wtf + OFF_WQKV, bqkv, Wa2q, ba2q, Wo, bo);

    // 3) mega launch 2: second hypernet stage (w1 x8 + wf = 1152 tiles)
    GOps m2 = {};
    for (int i = 0; i < 8; i++)
        m2.v[i] = { (float*)p_h1, wtf + OFF_WH1B, bh1b, (float*)p_w1, 256, 512, i * 64, 2, i * 128, 0 };
    m2.v[8] = { (float*)p_hf, wtf + OFF_WHFB, bhfb, (float*)p_wf, 256, 64, 0, 2, 1024, 0 };
    m2.v[9]  = { (float*)p_hf, wtf + OFF_WHFB, bhfb, (float*)p_wf, 256, 64, 0, 2, 0x7FFFFFFF, 0 };
    m2.v[10] = { (float*)p_hf, wtf + OFF_WHFB, bhfb, (float*)p_wf, 256, 64, 0, 2, 0x7FFFFFFF, 0 };
    packed_gemm<<<1152, 256, G_SMEM_BYTES>>>(m2, actions, agent_qs, W_act, W_q, b_act, b_q);

    // 4) final mix -> y
    final_kernel<<<2048, 256>>>(Wv2, bv2, out);
}